// round 15
// baseline (speedup 1.0000x reference)
#include <cuda_runtime.h>
#include <cuda_bf16.h>
#include <cuda_fp16.h>
#include <cstdint>

#define NN   50000
#define NE   600000
#define NT   (NE + NN)     // edges + self loops = 650000
#define D    128

// ---------------- device scratch (static, no runtime alloc) ----------------
__device__ __half g_X16[2][(size_t)NN * D];
__device__ __half g_P116[(size_t)NN * D];
__device__ __half g_P216[(size_t)NN * D];
__device__ int2  g_colew[NT];            // packed {col*D, bitcast(weight)}
__device__ int   g_rowptr[NN + 1];
__device__ int   g_deg[NN];              // zero-init at load; scan self-resets
__device__ int   g_epos[NE];             // per-edge slot within its row
__device__ float g_dinv[NN];
// Folded W (W0-W2, -W1, 2*W2) as fp16 hi/lo, transposed: [layer][n(128)][k(384)]
__device__ __half g_Wh16[3 * 128 * 384];
__device__ __half g_Wl16[3 * 128 * 384];

// ---------------- helpers ----------------
__device__ __forceinline__ uint2 half4_of(float4 v) {
    __half2 q01 = __floats2half2_rn(v.x, v.y);
    __half2 q23 = __floats2half2_rn(v.z, v.w);
    return make_uint2(*reinterpret_cast<uint32_t*>(&q01),
                      *reinterpret_cast<uint32_t*>(&q23));
}

#define CP16(daddr, gptr) \
    asm volatile("cp.async.cg.shared.global [%0], [%1], 16;" \
        :: "r"(daddr), "l"(gptr))
#define CP_COMMIT() asm volatile("cp.async.commit_group;" ::: "memory")
#define CP_WAIT(n)  asm volatile("cp.async.wait_group %0;" :: "n"(n) : "memory")
#define LDMX4(r0, r1, r2, r3, addr) \
    asm volatile("ldmatrix.sync.aligned.m8n8.x4.shared.b16 {%0,%1,%2,%3}, [%4];" \
        : "=r"(r0), "=r"(r1), "=r"(r2), "=r"(r3) : "r"(addr))

// ---------------- fused prep: count degrees (+slot) | input linear | W fold ----
#define NB_COUNT ((NE + 255) / 256)               // 2344
#define NB_FEAT  ((NN * (D / 4) + 255) / 256)     // 6250
#define NB_WPREP ((3 * 384 * 128 + 255) / 256)    // 576
#define NB_PREP  (NB_COUNT + NB_FEAT + NB_WPREP)

__global__ void prep_kernel(const int* __restrict__ dst,
                            const float* __restrict__ w,
                            const float* __restrict__ lw,
                            const float* __restrict__ lb,
                            const float* __restrict__ cheb_ws) {
    int b = blockIdx.x;
    int tid = threadIdx.x;
    if (b < NB_COUNT) {
        int e = b * 256 + tid;
        if (e < NE) g_epos[e] = atomicAdd(&g_deg[dst[e]], 1);
    } else if (b < NB_COUNT + NB_FEAT) {
        int i = (b - NB_COUNT) * 256 + tid;
        if (i >= NN * (D / 4)) return;
        int v  = i >> 5;
        int d4 = i & 31;
        float s = __ldg(w + v);
        float4 a = __ldg((const float4*)lw + d4);
        float4 bb = __ldg((const float4*)lb + d4);
        float4 r;
        r.x = fmaf(s, a.x, bb.x); r.y = fmaf(s, a.y, bb.y);
        r.z = fmaf(s, a.z, bb.z); r.w = fmaf(s, a.w, bb.w);
        *(uint2*)(g_X16[0] + (size_t)i * 4) = half4_of(r);
    } else {
        int i = (b - NB_COUNT - NB_FEAT) * 256 + tid;
        if (i >= 3 * 384 * 128) return;
        int l   = i / (384 * 128);
        int rem = i % (384 * 128);
        int k = rem >> 7;
        int n = rem & 127;
        int seg = k >> 7;
        int kin = k & 127;
        const float* WL0 = cheb_ws + (size_t)l * 384 * 128;
        float wv;
        if (seg == 0)      wv = __ldg(WL0 + (size_t)k * 128 + n) - __ldg(WL0 + (size_t)(256 + kin) * 128 + n);
        else if (seg == 1) wv = -__ldg(WL0 + (size_t)k * 128 + n);
        else               wv = 2.0f * __ldg(WL0 + (size_t)k * 128 + n);
        __half h = __float2half_rn(wv);
        size_t o = ((size_t)l * 128 + n) * 384 + k;
        g_Wh16[o] = h;
        g_Wl16[o] = __float2half_rn(wv - __half2float(h));
    }
}

// ---------------- CSR: single-block scan (smem-staged, self-resetting) --------
__global__ void scan_kernel() {
    extern __shared__ int ssm[];            // NN ints
    __shared__ int part[1024];
    const int T = 1024;
    const int CHUNK = (NN + T - 1) / T;     // 49
    int tid = threadIdx.x;

    for (int i = tid; i < NN; i += T) {
        ssm[i] = g_deg[i] + 1;              // +1 self loop
        g_deg[i] = 0;
    }
    __syncthreads();

    int start = tid * CHUNK;
    int end = start + CHUNK; if (end > NN) end = NN;
    int s = 0;
    for (int i = start; i < end; ++i) s += ssm[i];
    part[tid] = s;
    __syncthreads();
    for (int off = 1; off < T; off <<= 1) {
        int v = (tid >= off) ? part[tid - off] : 0;
        __syncthreads();
        part[tid] += v;
        __syncthreads();
    }
    int run = part[tid] - s;
    for (int i = start; i < end; ++i) {
        int v = ssm[i];
        ssm[i] = run;
        run += v;
    }
    __syncthreads();
    int total = part[T - 1];
    for (int i = tid; i < NN; i += T) {
        int rp = ssm[i];
        g_rowptr[i] = rp;
        int nxt = (i + 1 < NN) ? ssm[i + 1] : total;
        g_dinv[i] = rsqrtf((float)(nxt - rp));
    }
    if (tid == 0) g_rowptr[NN] = total;
}

__global__ void scatter_kernel(const int* __restrict__ src, const int* __restrict__ dst) {
    int e = blockIdx.x * blockDim.x + threadIdx.x;
    if (e >= NT) return;
    int s, d, pos;
    if (e < NE) {
        s = src[e]; d = dst[e];
        pos = g_rowptr[d] + g_epos[e];
    } else {
        s = d = e - NE;
        pos = g_rowptr[d + 1] - 1;           // self loop takes the last slot
    }
    g_colew[pos] = make_int2(s * D, __float_as_int(g_dinv[s] * g_dinv[d]));
}

// ---------------- SpMM: out = A_norm @ X (fp16 gather, unroll 8) ---------------
__global__ __launch_bounds__(256, 6)
void spmm_kernel(int mode, int flip) {
    const __half* __restrict__ X = (mode == 0) ? g_X16[flip] : g_P116;
    __half* __restrict__ OUT = (mode == 0) ? g_P116 : g_P216;

    int warp = (blockIdx.x * blockDim.x + threadIdx.x) >> 5;
    if (warp >= NN) return;
    int lane = threadIdx.x & 31;
    int beg = g_rowptr[warp];
    int end = g_rowptr[warp + 1];

    const __half* Xl4 = X + lane * 4;      // lane-fixed base; edge offset pre-scaled

    float4 acc = make_float4(0.f, 0.f, 0.f, 0.f);
    int p = beg;
    for (; p + 7 < end; p += 8) {
        int2 e0 = __ldg(g_colew + p);
        int2 e1 = __ldg(g_colew + p + 1);
        int2 e2 = __ldg(g_colew + p + 2);
        int2 e3 = __ldg(g_colew + p + 3);
        int2 e4 = __ldg(g_colew + p + 4);
        int2 e5 = __ldg(g_colew + p + 5);
        int2 e6 = __ldg(g_colew + p + 6);
        int2 e7 = __ldg(g_colew + p + 7);
        uint2 v0 = __ldg((const uint2*)(Xl4 + e0.x));
        uint2 v1 = __ldg((const uint2*)(Xl4 + e1.x));
        uint2 v2 = __ldg((const uint2*)(Xl4 + e2.x));
        uint2 v3 = __ldg((const uint2*)(Xl4 + e3.x));
        uint2 v4 = __ldg((const uint2*)(Xl4 + e4.x));
        uint2 v5 = __ldg((const uint2*)(Xl4 + e5.x));
        uint2 v6 = __ldg((const uint2*)(Xl4 + e6.x));
        uint2 v7 = __ldg((const uint2*)(Xl4 + e7.x));
#define ACC1(e, v) { \
        float w_ = __int_as_float((e).y); \
        float2 a_ = __half22float2(*reinterpret_cast<__half2*>(&(v).x)); \
        float2 b_ = __half22float2(*reinterpret_cast<__half2*>(&(v).y)); \
        acc.x = fmaf(w_, a_.x, acc.x); acc.y = fmaf(w_, a_.y, acc.y); \
        acc.z = fmaf(w_, b_.x, acc.z); acc.w = fmaf(w_, b_.y, acc.w); }
        ACC1(e0, v0) ACC1(e1, v1) ACC1(e2, v2) ACC1(e3, v3)
        ACC1(e4, v4) ACC1(e5, v5) ACC1(e6, v6) ACC1(e7, v7)
    }
    for (; p + 3 < end; p += 4) {
        int2 e0 = __ldg(g_colew + p);
        int2 e1 = __ldg(g_colew + p + 1);
        int2 e2 = __ldg(g_colew + p + 2);
        int2 e3 = __ldg(g_colew + p + 3);
        uint2 v0 = __ldg((const uint2*)(Xl4 + e0.x));
        uint2 v1 = __ldg((const uint2*)(Xl4 + e1.x));
        uint2 v2 = __ldg((const uint2*)(Xl4 + e2.x));
        uint2 v3 = __ldg((const uint2*)(Xl4 + e3.x));
        ACC1(e0, v0) ACC1(e1, v1) ACC1(e2, v2) ACC1(e3, v3)
    }
    for (; p < end; ++p) {
        int2 e0 = __ldg(g_colew + p);
        uint2 v0 = __ldg((const uint2*)(Xl4 + e0.x));
        ACC1(e0, v0)
    }
#undef ACC1

    *(uint2*)(OUT + (size_t)warp * D + lane * 4) = half4_of(acc);
}

// ======================= mma.sync fp16 GEMM (W hi/lo split, ldmatrix) ==========
// Y = relu(X0*W0' + P1*W1' + P2*W2' + b).
// A = stored fp16 features; W = Wh + Wl fp16 pair. 2 MMA terms: A*Wh + A*Wl.
// 8 warps, warp tile 64x32, m16n8k16.f16. 6 chunks K=64, double-buffered cp.async.
// Fragments loaded via ldmatrix.m8n8.x4 (conflict-free on the 36-word row pad).

#define ROW_W     36
#define BUF_W     (128 * ROW_W)
#define BUF_BYTES (BUF_W * 4)             // 18432
#define CH_BYTES  (3 * BUF_BYTES)         // 55296 (A, Bh, Bl)
#define GSMEM     (2 * CH_BYTES)          // 110592 dynamic smem

__device__ __forceinline__ void mma_f16(float* acc,
                                        uint32_t a0, uint32_t a1, uint32_t a2, uint32_t a3,
                                        uint32_t b0, uint32_t b1) {
    asm volatile(
        "mma.sync.aligned.m16n8k16.row.col.f32.f16.f16.f32 "
        "{%0,%1,%2,%3}, {%4,%5,%6,%7}, {%8,%9}, {%0,%1,%2,%3};"
        : "+f"(acc[0]), "+f"(acc[1]), "+f"(acc[2]), "+f"(acc[3])
        : "r"(a0), "r"(a1), "r"(a2), "r"(a3), "r"(b0), "r"(b1));
}

__device__ __forceinline__ void issue_chunk(
    uint32_t bb,
    const __half* __restrict__ X,
    const __half* __restrict__ WH, const __half* __restrict__ WL,
    int row0, int kk, int kbase, int tid)
{
#pragma unroll
    for (int i = 0; i < 4; ++i) {
        int idx = tid + i * 256;
        int r = idx >> 3, f = idx & 7;
        int grow = row0 + r; if (grow >= NN) grow = NN - 1;   // OOB rows discarded later
        CP16(bb + (uint32_t)(r * ROW_W + f * 4) * 4,
             X + (size_t)grow * D + kk + f * 8);
    }
#pragma unroll
    for (int i = 0; i < 4; ++i) {
        int idx = tid + i * 256;
        int n = idx >> 3, f = idx & 7;
        CP16(bb + BUF_BYTES + (uint32_t)(n * ROW_W + f * 4) * 4,
             WH + (size_t)n * 384 + kbase + f * 8);
    }
#pragma unroll
    for (int i = 0; i < 4; ++i) {
        int idx = tid + i * 256;
        int n = idx >> 3, f = idx & 7;
        CP16(bb + 2 * BUF_BYTES + (uint32_t)(n * ROW_W + f * 4) * 4,
             WL + (size_t)n * 384 + kbase + f * 8);
    }
}

__global__ __launch_bounds__(256, 1)
void gemm_mma_kernel(int layer, const float* __restrict__ bias, int flip,
                     const float* __restrict__ pw, const float* __restrict__ pb,
                     float* __restrict__ out) {
    extern __shared__ uint32_t dsm[];
    uint32_t sbase = (uint32_t)__cvta_generic_to_shared(dsm);

    const __half* A0 = g_X16[flip];
    __half*       Y16 = g_X16[flip ^ 1];
    const __half* WH = g_Wh16 + (size_t)layer * 128 * 384;
    const __half* WL = g_Wl16 + (size_t)layer * 128 * 384;
    bool last = (layer == 2);

    int tid = threadIdx.x;
    int wid = tid >> 5;
    int lane = tid & 31;
    int g   = lane >> 2;
    int tig = lane & 3;
    int row0 = blockIdx.x * 128;

    int m0w = (wid >> 2) * 64;
    int n0w = (wid & 3) * 32;

    // ldmatrix per-lane byte offsets (q = lane>>3 selects the 8x8 sub-matrix)
    int q = lane >> 3, lr = lane & 7;
    uint32_t a_lane_off = (uint32_t)((((q & 1) * 8 + lr) * ROW_W + (q >> 1) * 4) * 4);
    uint32_t b_lane_off = (uint32_t)((((q >> 1) * 8 + lr) * ROW_W + (q & 1) * 4) * 4);

    float acc[4][4][4];
#pragma unroll
    for (int mi = 0; mi < 4; ++mi)
#pragma unroll
        for (int ni = 0; ni < 4; ++ni)
#pragma unroll
            for (int qq = 0; qq < 4; ++qq) acc[mi][ni][qq] = 0.f;

    issue_chunk(sbase, A0, WH, WL, row0, 0, 0, tid);
    CP_COMMIT();

    for (int c = 0; c < 6; ++c) {
        if (c < 5) {
            int nc = c + 1;
            int srcI = nc >> 1, kk = (nc & 1) * 64;
            const __half* X = (srcI == 0) ? A0 : ((srcI == 1) ? g_P116 : g_P216);
            issue_chunk(sbase + (uint32_t)(nc & 1) * CH_BYTES,
                        X, WH, WL, row0, kk, srcI * 128 + kk, tid);
            CP_COMMIT();
            CP_WAIT(1);
        } else {
            CP_WAIT(0);
        }
        __syncthreads();

        uint32_t chb = sbase + (uint32_t)(c & 1) * CH_BYTES;

#pragma unroll
        for (int ks = 0; ks < 4; ++ks) {
            int kw = ks * 8;
            uint32_t af[4][4], bh[4][2], bl[4][2];
#pragma unroll
            for (int mi = 0; mi < 4; ++mi) {
                uint32_t addr = chb + (uint32_t)(((m0w + mi * 16) * ROW_W + kw) * 4) + a_lane_off;
                LDMX4(af[mi][0], af[mi][1], af[mi][2], af[mi][3], addr);
            }
#pragma unroll
            for (int pp = 0; pp < 2; ++pp) {
                uint32_t addr = chb + BUF_BYTES
                              + (uint32_t)(((n0w + pp * 16) * ROW_W + kw) * 4) + b_lane_off;
                LDMX4(bh[pp * 2][0], bh[pp * 2][1], bh[pp * 2 + 1][0], bh[pp * 2 + 1][1], addr);
                addr += BUF_BYTES;
                LDMX4(bl[pp * 2][0], bl[pp * 2][1], bl[pp * 2 + 1][0], bl[pp * 2 + 1][1], addr);
            }
#pragma unroll
            for (int mi = 0; mi < 4; ++mi)
#pragma unroll
                for (int ni = 0; ni < 4; ++ni) {
                    mma_f16(acc[mi][ni], af[mi][0], af[mi][1], af[mi][2], af[mi][3],
                            bh[ni][0], bh[ni][1]);
                    mma_f16(acc[mi][ni], af[mi][0], af[mi][1], af[mi][2], af[mi][3],
                            bl[ni][0], bl[ni][1]);
                }
        }
        __syncthreads();
    }

    if (!last) {
        // ---- epilogue: + bias, relu -> fp16 only ----
#pragma unroll
        for (int mi = 0; mi < 4; ++mi) {
            int r0 = row0 + m0w + mi * 16 + g;
            int r1 = r0 + 8;
#pragma unroll
            for (int ni = 0; ni < 4; ++ni) {
                int c = n0w + ni * 8 + 2 * tig;
                float2 bb = *(const float2*)(bias + c);
                if (r0 < NN) {
                    float vx = fmaxf(acc[mi][ni][0] + bb.x, 0.f);
                    float vy = fmaxf(acc[mi][ni][1] + bb.y, 0.f);
                    __half2 qv = __floats2half2_rn(vx, vy);
                    *(uint32_t*)(Y16 + (size_t)r0 * D + c) = *reinterpret_cast<uint32_t*>(&qv);
                }
                if (r1 < NN) {
                    float vx = fmaxf(acc[mi][ni][2] + bb.x, 0.f);
                    float vy = fmaxf(acc[mi][ni][3] + bb.y, 0.f);
                    __half2 qv = __floats2half2_rn(vx, vy);
                    *(uint32_t*)(Y16 + (size_t)r1 * D + c) = *reinterpret_cast<uint32_t*>(&qv);
                }
            }
        }
    } else {
        // ---- fused prediction head: out[r] = relu(acc + b) . pw + pb ----
        float* red = (float*)dsm;          // 128 floats, smem now free
        if (tid < 128) red[tid] = 0.f;
        __syncthreads();
#pragma unroll
        for (int mi = 0; mi < 4; ++mi) {
            float p0 = 0.f, p1 = 0.f;
#pragma unroll
            for (int ni = 0; ni < 4; ++ni) {
                int c = n0w + ni * 8 + 2 * tig;
                float2 bb = *(const float2*)(bias + c);
                float2 pp = __ldg((const float2*)(pw + c));
                float vx = fmaxf(acc[mi][ni][0] + bb.x, 0.f);
                float vy = fmaxf(acc[mi][ni][1] + bb.y, 0.f);
                p0 += vx * pp.x + vy * pp.y;
                vx = fmaxf(acc[mi][ni][2] + bb.x, 0.f);
                vy = fmaxf(acc[mi][ni][3] + bb.y, 0.f);
                p1 += vx * pp.x + vy * pp.y;
            }
            atomicAdd(&red[m0w + mi * 16 + g], p0);
            atomicAdd(&red[m0w + mi * 16 + 8 + g], p1);
        }
        __syncthreads();
        if (tid < 128) {
            int r = row0 + tid;
            if (r < NN) out[r] = red[tid] + __ldg(pb);
        }
    }
}

// ---------------- host launch ----------------
extern "C" void kernel_launch(void* const* d_in, const int* in_sizes, int n_in,
                              void* d_out, int out_size) {
    const float* weights = (const float*)d_in[0];
    const int*   src     = (const int*)d_in[1];
    const int*   dst     = (const int*)d_in[2];
    const float* lin_w   = (const float*)d_in[3];
    const float* lin_b   = (const float*)d_in[4];
    const float* cheb_ws = (const float*)d_in[5];
    const float* cheb_bs = (const float*)d_in[6];
    const float* pred_w  = (const float*)d_in[7];
    const float* pred_b  = (const float*)d_in[8];
    float* out = (float*)d_out;

    cudaFuncSetAttribute(gemm_mma_kernel,
                         cudaFuncAttributeMaxDynamicSharedMemorySize, GSMEM);
    cudaFuncSetAttribute(scan_kernel,
                         cudaFuncAttributeMaxDynamicSharedMemorySize, NN * 4);

    // fused count | feat | wprep, then scan, then scatter
    prep_kernel   <<<NB_PREP, 256>>>(dst, weights, lin_w, lin_b, cheb_ws);
    scan_kernel   <<<1, 1024, NN * 4>>>();
    scatter_kernel<<<(NT + 255) / 256, 256>>>(src, dst);

    const int spmm_blocks = (NN * 32 + 255) / 256;   // one warp per node
    const int gemm_blocks = (NN + 127) / 128;        // 391

    for (int l = 0; l < 3; ++l) {
        int flip = l & 1;
        spmm_kernel<<<spmm_blocks, 256>>>(0, flip);   // P1 = A~ X0
        spmm_kernel<<<spmm_blocks, 256>>>(1, flip);   // P2 = A~ P1
        gemm_mma_kernel<<<gemm_blocks, 256, GSMEM>>>(
            l, cheb_bs + (size_t)l * 128, flip, pred_w, pred_b, out);
        // inter-layer leaky_relu(relu(x)) == relu(x): no-op, skipped
    }
}

// round 16
// speedup vs baseline: 1.0550x; 1.0550x over previous
#include <cuda_runtime.h>
#include <cuda_bf16.h>
#include <cuda_fp16.h>
#include <cstdint>

#define NN   50000
#define NE   600000
#define NT   (NE + NN)     // edges + self loops = 650000
#define D    128

// ---------------- device scratch (static, no runtime alloc) ----------------
__device__ __half g_X16[2][(size_t)NN * D];
__device__ __half g_P116[(size_t)NN * D];
__device__ __half g_P216[(size_t)NN * D];
__device__ int2  g_colew[NT];            // packed {col*D, bitcast(weight)}
__device__ int   g_rowptr[NN + 1];
__device__ int   g_deg[NN];              // zero-init at load; scan self-resets
__device__ int   g_epos[NE];             // per-edge slot within its row
__device__ float g_dinv[NN];
// Folded W (W0-W2, -W1, 2*W2) as fp16 hi/lo, transposed: [layer][n(128)][k(384)]
__device__ __half g_Wh16[3 * 128 * 384];
__device__ __half g_Wl16[3 * 128 * 384];

// ---------------- helpers ----------------
__device__ __forceinline__ uint2 half4_of(float4 v) {
    __half2 q01 = __floats2half2_rn(v.x, v.y);
    __half2 q23 = __floats2half2_rn(v.z, v.w);
    return make_uint2(*reinterpret_cast<uint32_t*>(&q01),
                      *reinterpret_cast<uint32_t*>(&q23));
}

#define CP16(daddr, gptr) \
    asm volatile("cp.async.cg.shared.global [%0], [%1], 16;" \
        :: "r"(daddr), "l"(gptr))
#define CP_COMMIT() asm volatile("cp.async.commit_group;" ::: "memory")
#define CP_WAIT(n)  asm volatile("cp.async.wait_group %0;" :: "n"(n) : "memory")
#define LDMX4(r0, r1, r2, r3, addr) \
    asm volatile("ldmatrix.sync.aligned.m8n8.x4.shared.b16 {%0,%1,%2,%3}, [%4];" \
        : "=r"(r0), "=r"(r1), "=r"(r2), "=r"(r3) : "r"(addr))

// ---------------- fused prep: count degrees (+slot) | input linear | W fold ----
#define NB_COUNT ((NE + 255) / 256)               // 2344
#define NB_FEAT  ((NN * (D / 4) + 255) / 256)     // 6250
#define NB_WPREP ((3 * 384 * 128 + 255) / 256)    // 576
#define NB_PREP  (NB_COUNT + NB_FEAT + NB_WPREP)

__global__ void prep_kernel(const int* __restrict__ dst,
                            const float* __restrict__ w,
                            const float* __restrict__ lw,
                            const float* __restrict__ lb,
                            const float* __restrict__ cheb_ws) {
    int b = blockIdx.x;
    int tid = threadIdx.x;
    if (b < NB_COUNT) {
        int e = b * 256 + tid;
        if (e < NE) g_epos[e] = atomicAdd(&g_deg[dst[e]], 1);
    } else if (b < NB_COUNT + NB_FEAT) {
        int i = (b - NB_COUNT) * 256 + tid;
        if (i >= NN * (D / 4)) return;
        int v  = i >> 5;
        int d4 = i & 31;
        float s = __ldg(w + v);
        float4 a = __ldg((const float4*)lw + d4);
        float4 bb = __ldg((const float4*)lb + d4);
        float4 r;
        r.x = fmaf(s, a.x, bb.x); r.y = fmaf(s, a.y, bb.y);
        r.z = fmaf(s, a.z, bb.z); r.w = fmaf(s, a.w, bb.w);
        *(uint2*)(g_X16[0] + (size_t)i * 4) = half4_of(r);
    } else {
        int i = (b - NB_COUNT - NB_FEAT) * 256 + tid;
        if (i >= 3 * 384 * 128) return;
        int l   = i / (384 * 128);
        int rem = i % (384 * 128);
        int k = rem >> 7;
        int n = rem & 127;
        int seg = k >> 7;
        int kin = k & 127;
        const float* WL0 = cheb_ws + (size_t)l * 384 * 128;
        float wv;
        if (seg == 0)      wv = __ldg(WL0 + (size_t)k * 128 + n) - __ldg(WL0 + (size_t)(256 + kin) * 128 + n);
        else if (seg == 1) wv = -__ldg(WL0 + (size_t)k * 128 + n);
        else               wv = 2.0f * __ldg(WL0 + (size_t)k * 128 + n);
        __half h = __float2half_rn(wv);
        size_t o = ((size_t)l * 128 + n) * 384 + k;
        g_Wh16[o] = h;
        g_Wl16[o] = __float2half_rn(wv - __half2float(h));
    }
}

// ---------------- CSR: single-block scan (smem-staged, self-resetting) --------
__global__ void scan_kernel() {
    extern __shared__ int ssm[];            // NN ints
    __shared__ int part[1024];
    const int T = 1024;
    const int CHUNK = (NN + T - 1) / T;     // 49
    int tid = threadIdx.x;

    for (int i = tid; i < NN; i += T) {
        ssm[i] = g_deg[i] + 1;              // +1 self loop
        g_deg[i] = 0;
    }
    __syncthreads();

    int start = tid * CHUNK;
    int end = start + CHUNK; if (end > NN) end = NN;
    int s = 0;
    for (int i = start; i < end; ++i) s += ssm[i];
    part[tid] = s;
    __syncthreads();
    for (int off = 1; off < T; off <<= 1) {
        int v = (tid >= off) ? part[tid - off] : 0;
        __syncthreads();
        part[tid] += v;
        __syncthreads();
    }
    int run = part[tid] - s;
    for (int i = start; i < end; ++i) {
        int v = ssm[i];
        ssm[i] = run;
        run += v;
    }
    __syncthreads();
    int total = part[T - 1];
    for (int i = tid; i < NN; i += T) {
        int rp = ssm[i];
        g_rowptr[i] = rp;
        int nxt = (i + 1 < NN) ? ssm[i + 1] : total;
        g_dinv[i] = rsqrtf((float)(nxt - rp));
    }
    if (tid == 0) g_rowptr[NN] = total;
}

__global__ void scatter_kernel(const int* __restrict__ src, const int* __restrict__ dst) {
    int e = blockIdx.x * blockDim.x + threadIdx.x;
    if (e >= NT) return;
    int s, d, pos;
    if (e < NE) {
        s = src[e]; d = dst[e];
        pos = g_rowptr[d] + g_epos[e];
    } else {
        s = d = e - NE;
        pos = g_rowptr[d + 1] - 1;           // self loop takes the last slot
    }
    g_colew[pos] = make_int2(s * D, __float_as_int(g_dinv[s] * g_dinv[d]));
}

// ---------------- SpMM: out = A_norm @ X (fp16 gather, unroll 4 / occ 7) -------
__global__ __launch_bounds__(256, 7)
void spmm_kernel(int mode, int flip) {
    const __half* __restrict__ X = (mode == 0) ? g_X16[flip] : g_P116;
    __half* __restrict__ OUT = (mode == 0) ? g_P116 : g_P216;

    int warp = (blockIdx.x * blockDim.x + threadIdx.x) >> 5;
    if (warp >= NN) return;
    int lane = threadIdx.x & 31;
    int beg = g_rowptr[warp];
    int end = g_rowptr[warp + 1];

    const __half* Xl4 = X + lane * 4;      // lane-fixed base; edge offset pre-scaled

    float4 acc = make_float4(0.f, 0.f, 0.f, 0.f);
    int p = beg;
    for (; p + 3 < end; p += 4) {
        int2 e0 = __ldg(g_colew + p);
        int2 e1 = __ldg(g_colew + p + 1);
        int2 e2 = __ldg(g_colew + p + 2);
        int2 e3 = __ldg(g_colew + p + 3);
        uint2 v0 = __ldg((const uint2*)(Xl4 + e0.x));
        uint2 v1 = __ldg((const uint2*)(Xl4 + e1.x));
        uint2 v2 = __ldg((const uint2*)(Xl4 + e2.x));
        uint2 v3 = __ldg((const uint2*)(Xl4 + e3.x));
        float w0 = __int_as_float(e0.y);
        float w1 = __int_as_float(e1.y);
        float w2 = __int_as_float(e2.y);
        float w3 = __int_as_float(e3.y);
        float2 a0 = __half22float2(*reinterpret_cast<__half2*>(&v0.x));
        float2 b0 = __half22float2(*reinterpret_cast<__half2*>(&v0.y));
        float2 a1 = __half22float2(*reinterpret_cast<__half2*>(&v1.x));
        float2 b1 = __half22float2(*reinterpret_cast<__half2*>(&v1.y));
        float2 a2 = __half22float2(*reinterpret_cast<__half2*>(&v2.x));
        float2 b2 = __half22float2(*reinterpret_cast<__half2*>(&v2.y));
        float2 a3 = __half22float2(*reinterpret_cast<__half2*>(&v3.x));
        float2 b3 = __half22float2(*reinterpret_cast<__half2*>(&v3.y));
        acc.x = fmaf(w0, a0.x, acc.x); acc.y = fmaf(w0, a0.y, acc.y);
        acc.z = fmaf(w0, b0.x, acc.z); acc.w = fmaf(w0, b0.y, acc.w);
        acc.x = fmaf(w1, a1.x, acc.x); acc.y = fmaf(w1, a1.y, acc.y);
        acc.z = fmaf(w1, b1.x, acc.z); acc.w = fmaf(w1, b1.y, acc.w);
        acc.x = fmaf(w2, a2.x, acc.x); acc.y = fmaf(w2, a2.y, acc.y);
        acc.z = fmaf(w2, b2.x, acc.z); acc.w = fmaf(w2, b2.y, acc.w);
        acc.x = fmaf(w3, a3.x, acc.x); acc.y = fmaf(w3, a3.y, acc.y);
        acc.z = fmaf(w3, b3.x, acc.z); acc.w = fmaf(w3, b3.y, acc.w);
    }
    for (; p < end; ++p) {
        int2 e0 = __ldg(g_colew + p);
        float w0 = __int_as_float(e0.y);
        uint2 v0 = __ldg((const uint2*)(Xl4 + e0.x));
        float2 a0 = __half22float2(*reinterpret_cast<__half2*>(&v0.x));
        float2 b0 = __half22float2(*reinterpret_cast<__half2*>(&v0.y));
        acc.x = fmaf(w0, a0.x, acc.x); acc.y = fmaf(w0, a0.y, acc.y);
        acc.z = fmaf(w0, b0.x, acc.z); acc.w = fmaf(w0, b0.y, acc.w);
    }

    *(uint2*)(OUT + (size_t)warp * D + lane * 4) = half4_of(acc);
}

// ======================= mma.sync fp16 GEMM (W hi/lo split, ldmatrix) ==========
// Y = relu(X0*W0' + P1*W1' + P2*W2' + b).
// A = stored fp16 features; W = Wh + Wl fp16 pair. 2 MMA terms: A*Wh + A*Wl.
// 8 warps, warp tile 64x32, m16n8k16.f16. 6 chunks K=64, double-buffered cp.async.
// Fragments loaded via ldmatrix.m8n8.x4 (conflict-free on the 36-word row pad).

#define ROW_W     36
#define BUF_W     (128 * ROW_W)
#define BUF_BYTES (BUF_W * 4)             // 18432
#define CH_BYTES  (3 * BUF_BYTES)         // 55296 (A, Bh, Bl)
#define GSMEM     (2 * CH_BYTES)          // 110592 dynamic smem

__device__ __forceinline__ void mma_f16(float* acc,
                                        uint32_t a0, uint32_t a1, uint32_t a2, uint32_t a3,
                                        uint32_t b0, uint32_t b1) {
    asm volatile(
        "mma.sync.aligned.m16n8k16.row.col.f32.f16.f16.f32 "
        "{%0,%1,%2,%3}, {%4,%5,%6,%7}, {%8,%9}, {%0,%1,%2,%3};"
        : "+f"(acc[0]), "+f"(acc[1]), "+f"(acc[2]), "+f"(acc[3])
        : "r"(a0), "r"(a1), "r"(a2), "r"(a3), "r"(b0), "r"(b1));
}

__device__ __forceinline__ void issue_chunk(
    uint32_t bb,
    const __half* __restrict__ X,
    const __half* __restrict__ WH, const __half* __restrict__ WL,
    int row0, int kk, int kbase, int tid)
{
#pragma unroll
    for (int i = 0; i < 4; ++i) {
        int idx = tid + i * 256;
        int r = idx >> 3, f = idx & 7;
        int grow = row0 + r; if (grow >= NN) grow = NN - 1;   // OOB rows discarded later
        CP16(bb + (uint32_t)(r * ROW_W + f * 4) * 4,
             X + (size_t)grow * D + kk + f * 8);
    }
#pragma unroll
    for (int i = 0; i < 4; ++i) {
        int idx = tid + i * 256;
        int n = idx >> 3, f = idx & 7;
        CP16(bb + BUF_BYTES + (uint32_t)(n * ROW_W + f * 4) * 4,
             WH + (size_t)n * 384 + kbase + f * 8);
    }
#pragma unroll
    for (int i = 0; i < 4; ++i) {
        int idx = tid + i * 256;
        int n = idx >> 3, f = idx & 7;
        CP16(bb + 2 * BUF_BYTES + (uint32_t)(n * ROW_W + f * 4) * 4,
             WL + (size_t)n * 384 + kbase + f * 8);
    }
}

__global__ __launch_bounds__(256, 1)
void gemm_mma_kernel(int layer, const float* __restrict__ bias, int flip,
                     const float* __restrict__ pw, const float* __restrict__ pb,
                     float* __restrict__ out) {
    extern __shared__ uint32_t dsm[];
    uint32_t sbase = (uint32_t)__cvta_generic_to_shared(dsm);

    const __half* A0 = g_X16[flip];
    __half*       Y16 = g_X16[flip ^ 1];
    const __half* WH = g_Wh16 + (size_t)layer * 128 * 384;
    const __half* WL = g_Wl16 + (size_t)layer * 128 * 384;
    bool last = (layer == 2);

    int tid = threadIdx.x;
    int wid = tid >> 5;
    int lane = tid & 31;
    int g   = lane >> 2;
    int tig = lane & 3;
    int row0 = blockIdx.x * 128;

    int m0w = (wid >> 2) * 64;
    int n0w = (wid & 3) * 32;

    // ldmatrix per-lane byte offsets (q = lane>>3 selects the 8x8 sub-matrix)
    int q = lane >> 3, lr = lane & 7;
    uint32_t a_lane_off = (uint32_t)((((q & 1) * 8 + lr) * ROW_W + (q >> 1) * 4) * 4);
    uint32_t b_lane_off = (uint32_t)((((q >> 1) * 8 + lr) * ROW_W + (q & 1) * 4) * 4);

    float acc[4][4][4];
#pragma unroll
    for (int mi = 0; mi < 4; ++mi)
#pragma unroll
        for (int ni = 0; ni < 4; ++ni)
#pragma unroll
            for (int qq = 0; qq < 4; ++qq) acc[mi][ni][qq] = 0.f;

    issue_chunk(sbase, A0, WH, WL, row0, 0, 0, tid);
    CP_COMMIT();

    for (int c = 0; c < 6; ++c) {
        if (c < 5) {
            int nc = c + 1;
            int srcI = nc >> 1, kk = (nc & 1) * 64;
            const __half* X = (srcI == 0) ? A0 : ((srcI == 1) ? g_P116 : g_P216);
            issue_chunk(sbase + (uint32_t)(nc & 1) * CH_BYTES,
                        X, WH, WL, row0, kk, srcI * 128 + kk, tid);
            CP_COMMIT();
            CP_WAIT(1);
        } else {
            CP_WAIT(0);
        }
        __syncthreads();

        uint32_t chb = sbase + (uint32_t)(c & 1) * CH_BYTES;

#pragma unroll
        for (int ks = 0; ks < 4; ++ks) {
            int kw = ks * 8;
            uint32_t af[4][4], bh[4][2], bl[4][2];
#pragma unroll
            for (int mi = 0; mi < 4; ++mi) {
                uint32_t addr = chb + (uint32_t)(((m0w + mi * 16) * ROW_W + kw) * 4) + a_lane_off;
                LDMX4(af[mi][0], af[mi][1], af[mi][2], af[mi][3], addr);
            }
#pragma unroll
            for (int pp = 0; pp < 2; ++pp) {
                uint32_t addr = chb + BUF_BYTES
                              + (uint32_t)(((n0w + pp * 16) * ROW_W + kw) * 4) + b_lane_off;
                LDMX4(bh[pp * 2][0], bh[pp * 2][1], bh[pp * 2 + 1][0], bh[pp * 2 + 1][1], addr);
                addr += BUF_BYTES;
                LDMX4(bl[pp * 2][0], bl[pp * 2][1], bl[pp * 2 + 1][0], bl[pp * 2 + 1][1], addr);
            }
#pragma unroll
            for (int mi = 0; mi < 4; ++mi)
#pragma unroll
                for (int ni = 0; ni < 4; ++ni) {
                    mma_f16(acc[mi][ni], af[mi][0], af[mi][1], af[mi][2], af[mi][3],
                            bh[ni][0], bh[ni][1]);
                    mma_f16(acc[mi][ni], af[mi][0], af[mi][1], af[mi][2], af[mi][3],
                            bl[ni][0], bl[ni][1]);
                }
        }
        __syncthreads();
    }

    if (!last) {
        // ---- epilogue: + bias, relu -> fp16 only ----
#pragma unroll
        for (int mi = 0; mi < 4; ++mi) {
            int r0 = row0 + m0w + mi * 16 + g;
            int r1 = r0 + 8;
#pragma unroll
            for (int ni = 0; ni < 4; ++ni) {
                int c = n0w + ni * 8 + 2 * tig;
                float2 bb = *(const float2*)(bias + c);
                if (r0 < NN) {
                    float vx = fmaxf(acc[mi][ni][0] + bb.x, 0.f);
                    float vy = fmaxf(acc[mi][ni][1] + bb.y, 0.f);
                    __half2 qv = __floats2half2_rn(vx, vy);
                    *(uint32_t*)(Y16 + (size_t)r0 * D + c) = *reinterpret_cast<uint32_t*>(&qv);
                }
                if (r1 < NN) {
                    float vx = fmaxf(acc[mi][ni][2] + bb.x, 0.f);
                    float vy = fmaxf(acc[mi][ni][3] + bb.y, 0.f);
                    __half2 qv = __floats2half2_rn(vx, vy);
                    *(uint32_t*)(Y16 + (size_t)r1 * D + c) = *reinterpret_cast<uint32_t*>(&qv);
                }
            }
        }
    } else {
        // ---- fused prediction head: out[r] = relu(acc + b) . pw + pb ----
        float* red = (float*)dsm;          // 128 floats, smem now free
        if (tid < 128) red[tid] = 0.f;
        __syncthreads();
#pragma unroll
        for (int mi = 0; mi < 4; ++mi) {
            float p0 = 0.f, p1 = 0.f;
#pragma unroll
            for (int ni = 0; ni < 4; ++ni) {
                int c = n0w + ni * 8 + 2 * tig;
                float2 bb = *(const float2*)(bias + c);
                float2 pp = __ldg((const float2*)(pw + c));
                float vx = fmaxf(acc[mi][ni][0] + bb.x, 0.f);
                float vy = fmaxf(acc[mi][ni][1] + bb.y, 0.f);
                p0 += vx * pp.x + vy * pp.y;
                vx = fmaxf(acc[mi][ni][2] + bb.x, 0.f);
                vy = fmaxf(acc[mi][ni][3] + bb.y, 0.f);
                p1 += vx * pp.x + vy * pp.y;
            }
            atomicAdd(&red[m0w + mi * 16 + g], p0);
            atomicAdd(&red[m0w + mi * 16 + 8 + g], p1);
        }
        __syncthreads();
        if (tid < 128) {
            int r = row0 + tid;
            if (r < NN) out[r] = red[tid] + __ldg(pb);
        }
    }
}

// ---------------- host launch ----------------
extern "C" void kernel_launch(void* const* d_in, const int* in_sizes, int n_in,
                              void* d_out, int out_size) {
    const float* weights = (const float*)d_in[0];
    const int*   src     = (const int*)d_in[1];
    const int*   dst     = (const int*)d_in[2];
    const float* lin_w   = (const float*)d_in[3];
    const float* lin_b   = (const float*)d_in[4];
    const float* cheb_ws = (const float*)d_in[5];
    const float* cheb_bs = (const float*)d_in[6];
    const float* pred_w  = (const float*)d_in[7];
    const float* pred_b  = (const float*)d_in[8];
    float* out = (float*)d_out;

    cudaFuncSetAttribute(gemm_mma_kernel,
                         cudaFuncAttributeMaxDynamicSharedMemorySize, GSMEM);
    cudaFuncSetAttribute(scan_kernel,
                         cudaFuncAttributeMaxDynamicSharedMemorySize, NN * 4);

    // fused count | feat | wprep, then scan, then scatter
    prep_kernel   <<<NB_PREP, 256>>>(dst, weights, lin_w, lin_b, cheb_ws);
    scan_kernel   <<<1, 1024, NN * 4>>>();
    scatter_kernel<<<(NT + 255) / 256, 256>>>(src, dst);

    const int spmm_blocks = (NN * 32 + 255) / 256;   // one warp per node
    const int gemm_blocks = (NN + 127) / 128;        // 391

    for (int l = 0; l < 3; ++l) {
        int flip = l & 1;
        spmm_kernel<<<spmm_blocks, 256>>>(0, flip);   // P1 = A~ X0
        spmm_kernel<<<spmm_blocks, 256>>>(1, flip);   // P2 = A~ P1
        gemm_mma_kernel<<<gemm_blocks, 256, GSMEM>>>(
            l, cheb_bs + (size_t)l * 128, flip, pred_w, pred_b, out);
        // inter-layer leaky_relu(relu(x)) == relu(x): no-op, skipped
    }
}